// round 12
// baseline (speedup 1.0000x reference)
#include <cuda_runtime.h>
#include <cuda_fp16.h>
#include <math.h>

// Fixed shapes: features [16,512,768] f32, labels [16,512] i32. N = 8192.
#define H      768
#define H2     (H / 2)          // 384 float2 per row
#define NCLS   10
#define TPB    512
#define NBLK   256              // accumulation blocks (2/SM, 32 warps/SM)
#define RPB    32               // rows per block (N = NBLK*RPB = 8192)
#define RPW    2                // rows per warp in phase A (16 warps * 2 = 32)
#define CH     (NCLS * H)       // 7680 floats
#define CH2    (CH / 2)         // 3840 half2
#define CH8    (CH / 8)         // 960 uint4 (8 halfs) per partial
#define GRPSZ  16               // partials per reduce group
#define NGRP   (NBLK / GRPSZ)   // 16 groups
#define TPB2   256
#define NREDB  (NGRP * CH8 / TPB2)  // 60 reduce blocks
#define TEMPERATURE 0.07f
#define EPS    1e-12f

// Device scratch. g_cs/g_done/g_cnt_tot zero at load; restored by last block.
__device__ uint4    g_part[NBLK * CH8];   // fp16 partials, block-major (3.9 MB)
__device__ float    g_cs  [CH];
__device__ int      g_cnt_tot[NCLS];
__device__ unsigned g_done = 0;

// ---------------------------------------------------------------------------
// Kernel 1: Phase A warp-local norms, Phase B float2-owner accumulation from
// hot L2, coalesced uint4 fp16 flush.
// ---------------------------------------------------------------------------
__global__ __launch_bounds__(TPB, 2) void supcon_accum(
    const float* __restrict__ feat,
    const int*   __restrict__ labels)
{
    __shared__ float acc[CH];       // 30720 B
    __shared__ float inv[RPB];
    __shared__ int   labs[RPB];

    const int tid  = threadIdx.x;
    const int lane = tid & 31;
    const int warp = tid >> 5;
    const int bid  = blockIdx.x;
    const int row0 = bid * RPB;

    for (int i = tid; i < CH; i += TPB) acc[i] = 0.0f;

    if (tid < RPB) {
        int l = labels[row0 + tid];
        labs[tid] = min(max(l, 0), NCLS - 1);
    }

    // ---- Phase A: each of 16 warps computes norms of its 2 rows ----
    #pragma unroll
    for (int rr = 0; rr < RPW; ++rr) {
        const int r = warp * RPW + rr;
        const float4* x4 = reinterpret_cast<const float4*>(
                               feat + (size_t)(row0 + r) * H);
        float4 v[6];
        #pragma unroll
        for (int j = 0; j < 6; ++j)          // 6 independent LDG.128
            v[j] = x4[j * 32 + lane];
        float ss = 0.0f;
        #pragma unroll
        for (int j = 0; j < 6; ++j)
            ss += v[j].x*v[j].x + v[j].y*v[j].y + v[j].z*v[j].z + v[j].w*v[j].w;
        #pragma unroll
        for (int o = 16; o > 0; o >>= 1)
            ss += __shfl_xor_sync(0xffffffffu, ss, o);
        if (lane == 0)
            inv[r] = 1.0f / fmaxf(sqrtf(ss), EPS);
    }
    __syncthreads();

    // ---- Phase B: float2-owner accumulation (reads hit L2, no barriers) ----
    if (tid < H2) {
        float2* ap = reinterpret_cast<float2*>(acc);
        #pragma unroll
        for (int r0 = 0; r0 < RPB; r0 += 4) {
            float2 v[4];
            #pragma unroll
            for (int j = 0; j < 4; ++j)
                v[j] = reinterpret_cast<const float2*>(
                           feat + (size_t)(row0 + r0 + j) * H)[tid];
            #pragma unroll
            for (int j = 0; j < 4; ++j) {
                const float iv = inv[r0 + j];
                float2* a = ap + labs[r0 + j] * H2 + tid;
                float2 t = *a;
                t.x += v[j].x * iv;
                t.y += v[j].y * iv;
                *a = t;
            }
        }
    }
    __syncthreads();

    // ---- Flush fp16 partials as uint4 (8 halfs), block-major, coalesced ----
    {
        const float4* a4 = reinterpret_cast<const float4*>(acc);
        #pragma unroll
        for (int k = 0; k < 2; ++k) {
            const int i = k * TPB + tid;      // [0, 1024); CH8 = 960
            if (i < CH8) {
                float4 lo = a4[2 * i];
                float4 hi = a4[2 * i + 1];
                __half2 h0 = __floats2half2_rn(lo.x, lo.y);
                __half2 h1 = __floats2half2_rn(lo.z, lo.w);
                __half2 h2 = __floats2half2_rn(hi.x, hi.y);
                __half2 h3 = __floats2half2_rn(hi.z, hi.w);
                uint4 u;
                u.x = *reinterpret_cast<unsigned*>(&h0);
                u.y = *reinterpret_cast<unsigned*>(&h1);
                u.z = *reinterpret_cast<unsigned*>(&h2);
                u.w = *reinterpret_cast<unsigned*>(&h3);
                g_part[(size_t)bid * CH8 + i] = u;
            }
        }
        if (tid < NCLS) {
            int c = 0;
            #pragma unroll
            for (int r = 0; r < RPB; ++r) c += (labs[r] == tid);
            if (c > 0) atomicAdd(&g_cnt_tot[tid], c);
        }
    }
}

// ---------------------------------------------------------------------------
// Kernel 2: thread = (group of 16 partials, one uint4 column); 16 coalesced
// LDG.128 + 8 atomicAdds (16/addr total). Last block: f32 epilogue.
// ---------------------------------------------------------------------------
__global__ __launch_bounds__(TPB2) void supcon_reduce_final(
    float* __restrict__ out, int out_size, int N)
{
    __shared__ unsigned ticket_sh;
    __shared__ float sredA[8];
    __shared__ float sredP[8];
    __shared__ float loss_sh;

    const int tid  = threadIdx.x;
    const int lane = tid & 31;
    const int warp = tid >> 5;
    const int bid  = blockIdx.x;

    // ---- Reduce ----
    {
        const int task = bid * TPB2 + tid;        // [0, 15360)
        const int grp  = task / CH8;              // [0, 16)
        const int col  = task - grp * CH8;        // [0, 960)
        const uint4* base = g_part + (size_t)grp * GRPSZ * CH8 + col;
        float s0=0,s1=0,s2=0,s3=0,s4=0,s5=0,s6=0,s7=0;
        #pragma unroll
        for (int b = 0; b < GRPSZ; ++b) {         // 16 coalesced LDG.128
            uint4 u = base[(size_t)b * CH8];
            float2 f0 = __half22float2(*reinterpret_cast<__half2*>(&u.x));
            float2 f1 = __half22float2(*reinterpret_cast<__half2*>(&u.y));
            float2 f2 = __half22float2(*reinterpret_cast<__half2*>(&u.z));
            float2 f3 = __half22float2(*reinterpret_cast<__half2*>(&u.w));
            s0 += f0.x; s1 += f0.y; s2 += f1.x; s3 += f1.y;
            s4 += f2.x; s5 += f2.y; s6 += f3.x; s7 += f3.y;
        }
        float* dst = g_cs + 8 * col;
        atomicAdd(dst + 0, s0); atomicAdd(dst + 1, s1);
        atomicAdd(dst + 2, s2); atomicAdd(dst + 3, s3);
        atomicAdd(dst + 4, s4); atomicAdd(dst + 5, s5);
        atomicAdd(dst + 6, s6); atomicAdd(dst + 7, s7);
    }

    // ---- Last-block-done ticket ----
    __threadfence();
    __syncthreads();
    if (tid == 0) ticket_sh = atomicAdd(&g_done, 1u);
    __syncthreads();
    if (ticket_sh != NREDB - 1) return;
    __threadfence();   // acquire all g_cs adds

    // ---- Epilogue (f32) ----
    float p_all = 0.0f, p_pos = 0.0f;
    #pragma unroll
    for (int k = 0; k < H / TPB2; ++k) {          // 3 iterations
        const int h = k * TPB2 + tid;
        float sh = 0.0f;
        #pragma unroll
        for (int c = 0; c < NCLS; ++c) {
            float vv = g_cs[c * H + h];
            sh    += vv;
            p_pos += vv * vv;
        }
        p_all += sh * sh;
    }
    #pragma unroll
    for (int o = 16; o > 0; o >>= 1) {
        p_all += __shfl_xor_sync(0xffffffffu, p_all, o);
        p_pos += __shfl_xor_sync(0xffffffffu, p_pos, o);
    }
    if (lane == 0) { sredA[warp] = p_all; sredP[warp] = p_pos; }
    __syncthreads();

    if (tid == 0) {
        float A = 0.0f, P = 0.0f;
        #pragma unroll
        for (int w = 0; w < 8; ++w) { A += sredA[w]; P += sredP[w]; }
        float n_pos = 0.0f;
        #pragma unroll
        for (int c = 0; c < NCLS; ++c) {
            float nc = (float)g_cnt_tot[c];
            n_pos += nc * nc;
        }
        float Nf    = (float)N;
        float n_neg = Nf * Nf - n_pos;

        float pos_mean = (P / TEMPERATURE) / n_pos;
        float neg_mean = ((A - P) / TEMPERATURE) / n_neg;
        float d = neg_mean - pos_mean;
        loss_sh = (d > 0.0f) ? d + log1pf(expf(-d)) : log1pf(expf(d));
    }
    __syncthreads();
    for (int i = tid; i < out_size; i += TPB2) out[i] = loss_sh;

    // Self-clean scratch for the next graph replay.
    for (int i = tid; i < CH; i += TPB2) g_cs[i] = 0.0f;
    if (tid < NCLS) g_cnt_tot[tid] = 0;
    if (tid == 0)   g_done = 0u;
}

// ---------------------------------------------------------------------------
extern "C" void kernel_launch(void* const* d_in, const int* in_sizes, int n_in,
                              void* d_out, int out_size)
{
    const float* feat   = (const float*)d_in[0];
    const int*   labels = (const int*)d_in[1];
    float*       out    = (float*)d_out;
    const int N = in_sizes[1];   // 8192

    supcon_accum       <<<NBLK, TPB>>>(feat, labels);
    supcon_reduce_final<<<NREDB, TPB2>>>(out, out_size, N);
}

// round 13
// speedup vs baseline: 1.0155x; 1.0155x over previous
#include <cuda_runtime.h>
#include <cuda_fp16.h>
#include <math.h>

// Fixed shapes: features [16,512,768] f32, labels [16,512] i32. N = 8192.
#define H      768
#define H2     (H / 2)          // 384 float2 per row
#define NCLS   10
#define TPB    512
#define NBLK   256              // accumulation blocks (2/SM, 32 warps/SM)
#define RPB    32               // rows per block (N = NBLK*RPB = 8192)
#define RPW    2                // rows per warp in phase A (16 warps * 2 = 32)
#define CH     (NCLS * H)       // 7680 floats
#define CH8    (CH / 8)         // 960 uint4 (8 halfs) per partial
#define GRPSZ  16               // partials per reduce task
#define NGRP   (NBLK / GRPSZ)   // 16 groups
#define TPB2   256
#define NREDB  (NGRP * CH8 / TPB2)  // 60 reduce blocks
#define TEMPERATURE 0.07f
#define EPS    1e-12f

// Device scratch. g_cs/g_done/g_cnt_tot zero at load; restored by last block.
__device__ uint4    g_part[NBLK * CH8];   // fp16 partials, block-major (3.9 MB)
__device__ float    g_cs  [CH];
__device__ int      g_cnt_tot[NCLS];
__device__ unsigned g_done = 0;

// ---------------------------------------------------------------------------
// Kernel 1 (unchanged from R12): Phase A warp-local norms, Phase B float2-owner
// accumulation from hot L2, coalesced uint4 fp16 flush.
// ---------------------------------------------------------------------------
__global__ __launch_bounds__(TPB, 2) void supcon_accum(
    const float* __restrict__ feat,
    const int*   __restrict__ labels)
{
    __shared__ float acc[CH];       // 30720 B
    __shared__ float inv[RPB];
    __shared__ int   labs[RPB];

    const int tid  = threadIdx.x;
    const int lane = tid & 31;
    const int warp = tid >> 5;
    const int bid  = blockIdx.x;
    const int row0 = bid * RPB;

    for (int i = tid; i < CH; i += TPB) acc[i] = 0.0f;

    if (tid < RPB) {
        int l = labels[row0 + tid];
        labs[tid] = min(max(l, 0), NCLS - 1);
    }

    // ---- Phase A: each of 16 warps computes norms of its 2 rows ----
    #pragma unroll
    for (int rr = 0; rr < RPW; ++rr) {
        const int r = warp * RPW + rr;
        const float4* x4 = reinterpret_cast<const float4*>(
                               feat + (size_t)(row0 + r) * H);
        float4 v[6];
        #pragma unroll
        for (int j = 0; j < 6; ++j)          // 6 independent LDG.128
            v[j] = x4[j * 32 + lane];
        float ss = 0.0f;
        #pragma unroll
        for (int j = 0; j < 6; ++j)
            ss += v[j].x*v[j].x + v[j].y*v[j].y + v[j].z*v[j].z + v[j].w*v[j].w;
        #pragma unroll
        for (int o = 16; o > 0; o >>= 1)
            ss += __shfl_xor_sync(0xffffffffu, ss, o);
        if (lane == 0)
            inv[r] = 1.0f / fmaxf(sqrtf(ss), EPS);
    }
    __syncthreads();

    // ---- Phase B: float2-owner accumulation (reads hit L2, no barriers) ----
    if (tid < H2) {
        float2* ap = reinterpret_cast<float2*>(acc);
        #pragma unroll
        for (int r0 = 0; r0 < RPB; r0 += 4) {
            float2 v[4];
            #pragma unroll
            for (int j = 0; j < 4; ++j)
                v[j] = reinterpret_cast<const float2*>(
                           feat + (size_t)(row0 + r0 + j) * H)[tid];
            #pragma unroll
            for (int j = 0; j < 4; ++j) {
                const float iv = inv[r0 + j];
                float2* a = ap + labs[r0 + j] * H2 + tid;
                float2 t = *a;
                t.x += v[j].x * iv;
                t.y += v[j].y * iv;
                *a = t;
            }
        }
    }
    __syncthreads();

    // ---- Flush fp16 partials as uint4 (8 halfs), block-major, coalesced ----
    {
        const float4* a4 = reinterpret_cast<const float4*>(acc);
        #pragma unroll
        for (int k = 0; k < 2; ++k) {
            const int i = k * TPB + tid;      // [0, 1024); CH8 = 960
            if (i < CH8) {
                float4 lo = a4[2 * i];
                float4 hi = a4[2 * i + 1];
                __half2 h0 = __floats2half2_rn(lo.x, lo.y);
                __half2 h1 = __floats2half2_rn(lo.z, lo.w);
                __half2 h2 = __floats2half2_rn(hi.x, hi.y);
                __half2 h3 = __floats2half2_rn(hi.z, hi.w);
                uint4 u;
                u.x = *reinterpret_cast<unsigned*>(&h0);
                u.y = *reinterpret_cast<unsigned*>(&h1);
                u.z = *reinterpret_cast<unsigned*>(&h2);
                u.w = *reinterpret_cast<unsigned*>(&h3);
                g_part[(size_t)bid * CH8 + i] = u;
            }
        }
        if (tid < NCLS) {
            int c = 0;
            #pragma unroll
            for (int r = 0; r < RPB; ++r) c += (labs[r] == tid);
            if (c > 0) atomicAdd(&g_cnt_tot[tid], c);
        }
    }
}

// ---------------------------------------------------------------------------
// Kernel 2: thread = (group of 16 partials, one uint4 column).
// ALL 16 LDG.128 issued before any convert (explicit front-batch -> MLP 16),
// then 8 atomicAdds (123K total, 16/addr). Last block: f32 epilogue.
// ---------------------------------------------------------------------------
__global__ __launch_bounds__(TPB2) void supcon_reduce_final(
    float* __restrict__ out, int out_size, int N)
{
    __shared__ unsigned ticket_sh;
    __shared__ float sredA[8];
    __shared__ float sredP[8];
    __shared__ float loss_sh;

    const int tid  = threadIdx.x;
    const int lane = tid & 31;
    const int warp = tid >> 5;
    const int bid  = blockIdx.x;

    // ---- Reduce ----
    {
        const int task = bid * TPB2 + tid;        // [0, 15360)
        const int grp  = task / CH8;              // [0, 16)
        const int col  = task - grp * CH8;        // [0, 960)
        const uint4* base = g_part + (size_t)grp * GRPSZ * CH8 + col;

        // Front-batched loads: 16 independent LDG.128 in flight.
        uint4 u[GRPSZ];
        #pragma unroll
        for (int b = 0; b < GRPSZ; ++b)
            u[b] = base[(size_t)b * CH8];

        float s0=0,s1=0,s2=0,s3=0,s4=0,s5=0,s6=0,s7=0;
        #pragma unroll
        for (int b = 0; b < GRPSZ; ++b) {
            float2 f0 = __half22float2(*reinterpret_cast<__half2*>(&u[b].x));
            float2 f1 = __half22float2(*reinterpret_cast<__half2*>(&u[b].y));
            float2 f2 = __half22float2(*reinterpret_cast<__half2*>(&u[b].z));
            float2 f3 = __half22float2(*reinterpret_cast<__half2*>(&u[b].w));
            s0 += f0.x; s1 += f0.y; s2 += f1.x; s3 += f1.y;
            s4 += f2.x; s5 += f2.y; s6 += f3.x; s7 += f3.y;
        }
        float* dst = g_cs + 8 * col;
        atomicAdd(dst + 0, s0); atomicAdd(dst + 1, s1);
        atomicAdd(dst + 2, s2); atomicAdd(dst + 3, s3);
        atomicAdd(dst + 4, s4); atomicAdd(dst + 5, s5);
        atomicAdd(dst + 6, s6); atomicAdd(dst + 7, s7);
    }

    // ---- Last-block-done ticket ----
    __threadfence();
    __syncthreads();
    if (tid == 0) ticket_sh = atomicAdd(&g_done, 1u);
    __syncthreads();
    if (ticket_sh != NREDB - 1) return;
    __threadfence();   // acquire all g_cs adds

    // ---- Epilogue (f32) ----
    float p_all = 0.0f, p_pos = 0.0f;
    #pragma unroll
    for (int k = 0; k < H / TPB2; ++k) {          // 3 iterations
        const int h = k * TPB2 + tid;
        float sh = 0.0f;
        #pragma unroll
        for (int c = 0; c < NCLS; ++c) {
            float vv = g_cs[c * H + h];
            sh    += vv;
            p_pos += vv * vv;
        }
        p_all += sh * sh;
    }
    #pragma unroll
    for (int o = 16; o > 0; o >>= 1) {
        p_all += __shfl_xor_sync(0xffffffffu, p_all, o);
        p_pos += __shfl_xor_sync(0xffffffffu, p_pos, o);
    }
    if (lane == 0) { sredA[warp] = p_all; sredP[warp] = p_pos; }
    __syncthreads();

    if (tid == 0) {
        float A = 0.0f, P = 0.0f;
        #pragma unroll
        for (int w = 0; w < 8; ++w) { A += sredA[w]; P += sredP[w]; }
        float n_pos = 0.0f;
        #pragma unroll
        for (int c = 0; c < NCLS; ++c) {
            float nc = (float)g_cnt_tot[c];
            n_pos += nc * nc;
        }
        float Nf    = (float)N;
        float n_neg = Nf * Nf - n_pos;

        float pos_mean = (P / TEMPERATURE) / n_pos;
        float neg_mean = ((A - P) / TEMPERATURE) / n_neg;
        float d = neg_mean - pos_mean;
        loss_sh = (d > 0.0f) ? d + log1pf(expf(-d)) : log1pf(expf(d));
    }
    __syncthreads();
    for (int i = tid; i < out_size; i += TPB2) out[i] = loss_sh;

    // Self-clean scratch for the next graph replay.
    for (int i = tid; i < CH; i += TPB2) g_cs[i] = 0.0f;
    if (tid < NCLS) g_cnt_tot[tid] = 0;
    if (tid == 0)   g_done = 0u;
}

// ---------------------------------------------------------------------------
extern "C" void kernel_launch(void* const* d_in, const int* in_sizes, int n_in,
                              void* d_out, int out_size)
{
    const float* feat   = (const float*)d_in[0];
    const int*   labels = (const int*)d_in[1];
    float*       out    = (float*)d_out;
    const int N = in_sizes[1];   // 8192

    supcon_accum       <<<NBLK, TPB>>>(feat, labels);
    supcon_reduce_final<<<NREDB, TPB2>>>(out, out_size, N);
}

// round 14
// speedup vs baseline: 1.1026x; 1.0858x over previous
#include <cuda_runtime.h>
#include <math.h>

// Fixed shapes: features [16,512,768] f32, labels [16,512] i32. N = 8192.
#define H      768
#define H2     (H / 2)          // 384 float2 per row
#define NCLS   10
#define TPB    512
#define NBLK   256              // accumulation blocks (2/SM)
#define RPB    32               // rows per block (N = NBLK*RPB = 8192)
#define RPW    2                // rows per warp in phase A (16 warps * 2 = 32)
#define CH     (NCLS * H)       // 7680 floats
#define CH4    (CH / 4)         // 1920 float4
#define TEMPERATURE 0.07f
#define EPS    1e-12f

// Device scratch. Zero at module load; restored to zero by the last block
// every run (self-cleaning for graph replay). NO partial buffer at all.
__device__ float    g_cs[CH];       // global class sums (vector-RED target)
__device__ int      g_cnt_tot[NCLS];
__device__ unsigned g_done = 0;

// Vector reduction: one RED.F32x4 to global memory (sm_90+).
__device__ __forceinline__ void red_add_v4(float* addr, float4 v)
{
    asm volatile("red.global.add.v4.f32 [%0], {%1, %2, %3, %4};"
                 :: "l"(addr), "f"(v.x), "f"(v.y), "f"(v.z), "f"(v.w)
                 : "memory");
}

// ---------------------------------------------------------------------------
// Single kernel: Phase A warp-local norms, Phase B float2-owner accumulation
// from hot L2, flush via RED.F32x4 into g_cs, last-block f32 epilogue.
// ---------------------------------------------------------------------------
__global__ __launch_bounds__(TPB, 2) void supcon_all(
    const float* __restrict__ feat,
    const int*   __restrict__ labels,
    float*       __restrict__ out,
    int out_size, int N)
{
    __shared__ float acc[CH];       // 30720 B
    __shared__ float inv[RPB];
    __shared__ int   labs[RPB];
    __shared__ unsigned ticket_sh;
    __shared__ float sredA[16];
    __shared__ float sredP[16];
    __shared__ float loss_sh;

    const int tid  = threadIdx.x;
    const int lane = tid & 31;
    const int warp = tid >> 5;
    const int bid  = blockIdx.x;
    const int row0 = bid * RPB;

    for (int i = tid; i < CH; i += TPB) acc[i] = 0.0f;

    if (tid < RPB) {
        int l = labels[row0 + tid];
        labs[tid] = min(max(l, 0), NCLS - 1);
    }

    // ---- Phase A: each of 16 warps computes norms of its 2 rows ----
    #pragma unroll
    for (int rr = 0; rr < RPW; ++rr) {
        const int r = warp * RPW + rr;
        const float4* x4 = reinterpret_cast<const float4*>(
                               feat + (size_t)(row0 + r) * H);
        float4 v[6];
        #pragma unroll
        for (int j = 0; j < 6; ++j)          // 6 independent LDG.128
            v[j] = x4[j * 32 + lane];
        float ss = 0.0f;
        #pragma unroll
        for (int j = 0; j < 6; ++j)
            ss += v[j].x*v[j].x + v[j].y*v[j].y + v[j].z*v[j].z + v[j].w*v[j].w;
        #pragma unroll
        for (int o = 16; o > 0; o >>= 1)
            ss += __shfl_xor_sync(0xffffffffu, ss, o);
        if (lane == 0)
            inv[r] = 1.0f / fmaxf(sqrtf(ss), EPS);
    }
    __syncthreads();

    // ---- Phase B: float2-owner accumulation (reads hit L2, no barriers) ----
    if (tid < H2) {
        float2* ap = reinterpret_cast<float2*>(acc);
        #pragma unroll
        for (int r0 = 0; r0 < RPB; r0 += 4) {
            float2 v[4];
            #pragma unroll
            for (int j = 0; j < 4; ++j)
                v[j] = reinterpret_cast<const float2*>(
                           feat + (size_t)(row0 + r0 + j) * H)[tid];
            #pragma unroll
            for (int j = 0; j < 4; ++j) {
                const float iv = inv[r0 + j];
                float2* a = ap + labs[r0 + j] * H2 + tid;
                float2 t = *a;
                t.x += v[j].x * iv;
                t.y += v[j].y * iv;
                *a = t;
            }
        }
    }
    __syncthreads();

    // ---- Flush: vector reductions straight into g_cs (no partial buffer) ----
    {
        const float4* a4 = reinterpret_cast<const float4*>(acc);
        #pragma unroll
        for (int k = 0; k < 4; ++k) {
            const int i = k * TPB + tid;    // [0, 2048); CH4 = 1920
            if (i < CH4) {
                float4 v = a4[i];
                // Skip all-zero rows? Most acc entries are nonzero; just issue.
                red_add_v4(g_cs + 4 * i, v);
            }
        }
        if (tid < NCLS) {
            int c = 0;
            #pragma unroll
            for (int r = 0; r < RPB; ++r) c += (labs[r] == tid);
            if (c > 0) atomicAdd(&g_cnt_tot[tid], c);
        }
    }

    // ---- Last-block ticket (no spinning: last arriver does the epilogue) ----
    __threadfence();
    __syncthreads();
    if (tid == 0) ticket_sh = atomicAdd(&g_done, 1u);
    __syncthreads();
    if (ticket_sh != NBLK - 1) return;
    __threadfence();   // acquire: all other blocks' REDs are visible

    // ---- Epilogue (f32) ----
    float p_all = 0.0f, p_pos = 0.0f;
    for (int h = tid; h < H; h += TPB) {     // tid<256 does 2 cols, else 1
        float sh = 0.0f;
        #pragma unroll
        for (int c = 0; c < NCLS; ++c) {
            float vv = g_cs[c * H + h];
            sh    += vv;
            p_pos += vv * vv;
        }
        p_all += sh * sh;
    }
    #pragma unroll
    for (int o = 16; o > 0; o >>= 1) {
        p_all += __shfl_xor_sync(0xffffffffu, p_all, o);
        p_pos += __shfl_xor_sync(0xffffffffu, p_pos, o);
    }
    if (lane == 0) { sredA[warp] = p_all; sredP[warp] = p_pos; }
    __syncthreads();

    if (tid == 0) {
        float A = 0.0f, P = 0.0f;
        #pragma unroll
        for (int w = 0; w < 16; ++w) { A += sredA[w]; P += sredP[w]; }
        float n_pos = 0.0f;
        #pragma unroll
        for (int c = 0; c < NCLS; ++c) {
            float nc = (float)g_cnt_tot[c];
            n_pos += nc * nc;
        }
        float Nf    = (float)N;
        float n_neg = Nf * Nf - n_pos;

        float pos_mean = (P / TEMPERATURE) / n_pos;
        float neg_mean = ((A - P) / TEMPERATURE) / n_neg;
        float d = neg_mean - pos_mean;
        loss_sh = (d > 0.0f) ? d + log1pf(expf(-d)) : log1pf(expf(d));
    }
    __syncthreads();
    for (int i = tid; i < out_size; i += TPB) out[i] = loss_sh;

    // Self-clean for the next graph replay.
    for (int i = tid; i < CH; i += TPB) g_cs[i] = 0.0f;
    if (tid < NCLS) g_cnt_tot[tid] = 0;
    if (tid == 0)   g_done = 0u;
}

// ---------------------------------------------------------------------------
extern "C" void kernel_launch(void* const* d_in, const int* in_sizes, int n_in,
                              void* d_out, int out_size)
{
    const float* feat   = (const float*)d_in[0];
    const int*   labels = (const int*)d_in[1];
    float*       out    = (float*)d_out;
    const int N = in_sizes[1];   // 8192

    supcon_all<<<NBLK, TPB>>>(feat, labels, out, out_size, N);
}